// round 15
// baseline (speedup 1.0000x reference)
#include <cuda_runtime.h>
#include <cuda_bf16.h>
#include <cstdint>

#define NN   50000
#define DEG  16
#define FD   160
#define HD   160
#define GD   640
#define OC   128
#define KHH  160

// prep (fp32) config — proven machinery
#define PTM  64
#define PNT  512
#define PKC  16
#define PNCH (KHH/PKC)
#define PCHF (PKC*GD)
#define PCHB (PCHF*4)

// cluster main kernel config
#define TM   64
#define CNT  512                   // 16 warps = 4 M x 4 N (N within quarter)
#define HBUF1 43008                // bytes per h buffer (2 planes x 64 x 336B)
#define HPL   21504                // plane stride bytes
#define SM_W  86016                // resident W quarter (both planes), 102400B
#define WPL   51200                // W plane stride bytes
#define SM_CSTC 188416             // cst [5][512] f32 = 10240
#define SM_SRCC 198656             // [2][64] ints
#define SM_CL  199168

typedef unsigned long long ull;

// ---------------- device scratch ----------------
__device__ float g_hin[NN * FD];
__device__ float g_WihP[KHH * HD * 4];   // [k][m][4]
__device__ float g_bias[GD];             // [m][4]
__device__ float g_WlP[KHH * OC];
__device__ float g_WrP[KHH * OC];
__device__ float g_P[NN * GD];           // [node][4m+g], biases folded
__device__ float g_Q[NN * OC];
// Whh bf16 split: [pl 2][q 4][kc 10][n 160][16]
__device__ __align__(16) __nv_bfloat16 g_Wb[2 * 4 * 10 * 160 * 16];

// ---------------- helpers ----------------
__device__ __forceinline__ ull pack2(float lo, float hi) {
    ull v; asm("mov.b64 %0, {%1, %2};" : "=l"(v) : "f"(lo), "f"(hi)); return v;
}
__device__ __forceinline__ void unpack2(ull v, float& lo, float& hi) {
    asm("mov.b64 {%0, %1}, %2;" : "=f"(lo), "=f"(hi) : "l"(v));
}
__device__ __forceinline__ void fma2(ull& d, ull a, ull b) {
    asm("fma.rn.f32x2 %0, %1, %2, %0;" : "+l"(d) : "l"(a), "l"(b));
}
__device__ __forceinline__ void ldsv2(uint32_t a, ull& x, ull& y) {
    asm("ld.shared.v2.u64 {%0,%1}, [%2];" : "=l"(x), "=l"(y) : "r"(a));
}
__device__ __forceinline__ void ldsm4(uint32_t* r, uint32_t a) {
    asm volatile("ldmatrix.sync.aligned.m8n8.x4.shared.b16 {%0,%1,%2,%3}, [%4];"
                 : "=r"(r[0]), "=r"(r[1]), "=r"(r[2]), "=r"(r[3]) : "r"(a));
}
__device__ __forceinline__ void ldsm2(uint32_t* r, uint32_t a) {
    asm volatile("ldmatrix.sync.aligned.m8n8.x2.shared.b16 {%0,%1}, [%2];"
                 : "=r"(r[0]), "=r"(r[1]) : "r"(a));
}
__device__ __forceinline__ void cp16(uint32_t s, const void* g) {
    asm volatile("cp.async.ca.shared.global [%0], [%1], 16;" :: "r"(s), "l"(g));
}
__device__ __forceinline__ void cpcommit() { asm volatile("cp.async.commit_group;"); }
template<int N> __device__ __forceinline__ void cpwait() {
    asm volatile("cp.async.wait_group %0;" :: "n"(N));
}
__device__ __forceinline__ float sigm(float x) { return __fdividef(1.f, 1.f + __expf(-x)); }
__device__ __forceinline__ float tanhfast(float x) {
    return __fdividef(2.f, 1.f + __expf(-2.f * x)) - 1.f;
}
__device__ __forceinline__ void mma_bf16(float* d, const uint32_t* a, uint32_t b0, uint32_t b1) {
    asm volatile("mma.sync.aligned.m16n8k16.row.col.f32.bf16.bf16.f32 "
                 "{%0,%1,%2,%3}, {%4,%5,%6,%7}, {%8,%9}, {%0,%1,%2,%3};"
                 : "+f"(d[0]), "+f"(d[1]), "+f"(d[2]), "+f"(d[3])
                 : "r"(a[0]), "r"(a[1]), "r"(a[2]), "r"(a[3]), "r"(b0), "r"(b1));
}
__device__ __forceinline__ uint32_t clrank() {
    uint32_t r; asm("mov.u32 %0, %%cluster_ctarank;" : "=r"(r)); return r;
}
__device__ __forceinline__ uint32_t mapa_rk(uint32_t addr, uint32_t rk) {
    uint32_t r;
    asm("mapa.shared::cluster.u32 %0, %1, %2;" : "=r"(r) : "r"(addr), "r"(rk));
    return r;
}
__device__ __forceinline__ void stcl16(uint32_t a, uint16_t v) {
    asm volatile("st.shared::cluster.u16 [%0], %1;" :: "r"(a), "h"(v) : "memory");
}
__device__ __forceinline__ void cluster_sync() {
    asm volatile("barrier.cluster.arrive.aligned;" ::: "memory");
    asm volatile("barrier.cluster.wait.aligned;" ::: "memory");
}

// ---------------- prep kernels (unchanged, proven) ----------------
__global__ void prep_hin(const float* __restrict__ x, const int* __restrict__ tids,
                         const float* __restrict__ emb) {
    int i = blockIdx.x * blockDim.x + threadIdx.x;
    if (i >= NN * FD) return;
    int n = i / FD, c = i % FD;
    g_hin[i] = (c < 128) ? x[n * 128 + c] : emb[tids[n] * 32 + (c - 128)];
}

__global__ void prep_w(const float* __restrict__ Wih, const float* __restrict__ Whh,
                       const float* __restrict__ bih, const float* __restrict__ bhh,
                       const float* __restrict__ Wl,  const float* __restrict__ Wr) {
    int i = blockIdx.x * blockDim.x + threadIdx.x;
    if (i < KHH * HD * 4) {
        int g = i & 3, m = (i >> 2) % HD, k = (i >> 2) / HD;
        g_WihP[i] = Wih[(g * HD + m) * FD + k];
    }
    if (i < GD) {
        int m = i >> 2, g = i & 3;
        g_bias[i] = bih[g * HD + m] + bhh[g * HD + m];
    }
    if (i < KHH * OC) {
        int k = i / OC, j = i % OC;
        g_WlP[i] = Wl[j * FD + k];
        g_WrP[i] = Wr[j * FD + k];
    }
    if (i < 2 * 4 * 10 * 160 * 16) {
        int kk = i & 15;
        int n  = (i >> 4) % 160;
        int kc = (i / 2560) % 10;
        int q  = (i / 25600) % 4;
        int pl = i / 102400;
        int k = kc * 16 + kk;
        int gcl = q * 160 + n;
        int m = gcl >> 2, g = gcl & 3;
        float w = Whh[(g * HD + m) * HD + k];
        __nv_bfloat16 hb = __float2bfloat16(w);
        g_Wb[i] = pl ? __float2bfloat16(w - __bfloat162float(hb)) : hb;
    }
}

__device__ __forceinline__ void pstage(const float* gsrc, uint32_t sdst, int tid) {
#pragma unroll
    for (int u = 0; u < 5; u++)
        cp16(sdst + (uint32_t)(tid * 16 + u * 8192), gsrc + tid * 4 + u * 2048);
    cpcommit();
}
__device__ __forceinline__ void pgemm(const float* __restrict__ gW, uint32_t wsbase,
                                      const float* __restrict__ hrow, int tid, int c,
                                      ull accIF[4][5], ull accGO[4][5]) {
    pstage(gW, wsbase, tid);
    pstage(gW + PCHF, wsbase + PCHB, tid);
    for (int ch = 0; ch < PNCH; ch++) {
        if (ch == PNCH - 1) cpwait<0>(); else cpwait<1>();
        __syncthreads();
        const uint32_t wb0 = wsbase + (uint32_t)(ch & 1) * PCHB;
#pragma unroll
        for (int kq = 0; kq < 4; kq++) {
            float4 a4[4];
#pragma unroll
            for (int i = 0; i < 4; i++)
                a4[i] = *(const float4*)&hrow[i * KHH + ch * PKC + kq * 4];
#pragma unroll
            for (int k2 = 0; k2 < 4; k2++) {
                ull a2[4];
#pragma unroll
                for (int i = 0; i < 4; i++) {
                    float a = (k2 == 0) ? a4[i].x : (k2 == 1) ? a4[i].y
                             : (k2 == 2) ? a4[i].z : a4[i].w;
                    a2[i] = pack2(a, a);
                }
                const uint32_t wb = wb0 + (uint32_t)((kq * 4 + k2) * 2560 + c * 16);
#pragma unroll
                for (int n = 0; n < 5; n++) {
                    ull wif, wgo;
                    ldsv2(wb + (uint32_t)(n * 512), wif, wgo);
#pragma unroll
                    for (int i = 0; i < 4; i++) {
                        fma2(accIF[i][n], a2[i], wif);
                        fma2(accGO[i][n], a2[i], wgo);
                    }
                }
            }
        }
        __syncthreads();
        if (ch < PNCH - 2) pstage(gW + (ch + 2) * PCHF, wsbase + (uint32_t)(ch & 1) * PCHB, tid);
    }
}

__global__ void __launch_bounds__(PNT, 1)
prep_PQ(const float* __restrict__ bl) {
    extern __shared__ float sm[];
    float* hs = sm;
    const uint32_t sbase = (uint32_t)__cvta_generic_to_shared(sm);
    const uint32_t wsbase = sbase + PTM * KHH * 4;
    const int tid = threadIdx.x, c = tid & 31, warp = tid >> 5;
    const int nodeBase = blockIdx.x * PTM;
    float* hrow = hs + warp * 4 * KHH;

#pragma unroll
    for (int u = 0; u < 5; u++) {
        int idx4 = tid + u * PNT;
        int r = idx4 / 40, col4 = idx4 % 40;
        int node = nodeBase + r; if (node >= NN) node = NN - 1;
        ((float4*)hs)[idx4] = ((const float4*)g_hin)[node * 40 + col4];
    }
    __syncthreads();

    ull accIF[4][5], accGO[4][5];
#pragma unroll
    for (int n = 0; n < 5; n++) {
        float4 b = ((const float4*)g_bias)[n * 32 + c];
#pragma unroll
        for (int i = 0; i < 4; i++) {
            accIF[i][n] = pack2(b.x, b.y);
            accGO[i][n] = pack2(b.z, b.w);
        }
    }
    pgemm(g_WihP, wsbase, hrow, tid, c, accIF, accGO);

#pragma unroll
    for (int i = 0; i < 4; i++) {
        int node = nodeBase + warp * 4 + i;
        if (node < NN) {
#pragma unroll
            for (int n = 0; n < 5; n++) {
                float4 o;
                unpack2(accIF[i][n], o.x, o.y);
                unpack2(accGO[i][n], o.z, o.w);
                ((float4*)g_P)[node * 160 + n * 32 + c] = o;
            }
        }
    }

    __syncthreads();
    float* Wfs = hs + PTM * KHH;
    for (int u = tid; u < KHH * OC / 4; u += PNT)
        ((float4*)Wfs)[u] = ((const float4*)g_WrP)[u];
    __syncthreads();

    float4 q[4];
    float4 blv = ((const float4*)bl)[c];
#pragma unroll
    for (int i = 0; i < 4; i++) q[i] = blv;
    for (int k = 0; k < KHH; k++) {
        float4 w = ((const float4*)Wfs)[k * 32 + c];
#pragma unroll
        for (int i = 0; i < 4; i++) {
            float a = hrow[i * KHH + k];
            q[i].x = fmaf(a, w.x, q[i].x);
            q[i].y = fmaf(a, w.y, q[i].y);
            q[i].z = fmaf(a, w.z, q[i].z);
            q[i].w = fmaf(a, w.w, q[i].w);
        }
    }
#pragma unroll
    for (int i = 0; i < 4; i++) {
        int node = nodeBase + warp * 4 + i;
        if (node < NN) ((float4*)g_Q)[node * 32 + c] = q[i];
    }
}

// ---------------- cluster main kernel ----------------
// smem: h[2buf][2pl][64][336B] | W resident [2pl][10kc][160n][32B,XOR16] | cst[5][512] | src[2][64]
__global__ void __launch_bounds__(CNT, 1) __cluster_dims__(4, 1, 1)
lstm_cluster(const int* __restrict__ esrc, float* __restrict__ out) {
    extern __shared__ char smraw[];
    __nv_bfloat16* hB = (__nv_bfloat16*)smraw;
    float* cst = (float*)(smraw + SM_CSTC);
    int*   srcS = (int*)(smraw + SM_SRCC);
    const uint32_t sbase = (uint32_t)__cvta_generic_to_shared(smraw);
    const uint32_t wres = sbase + SM_W;

    const int tid = threadIdx.x, lane = tid & 31, warp = tid >> 5;
    const int q2 = lane & 3, r8 = lane >> 2;
    const int mg = warp & 3, ng = warp >> 2;       // 4 M-groups x 4 N-groups
    const int lrow = lane & 15, lkoff = (lane >> 4) * 16;
    const uint32_t rank = clrank();
    const int nodeBase = (blockIdx.x >> 2) * TM;

    // ---- prologue: stage resident W quarter (XOR-swizzled 32B rows), zero h/cst
    {
        const __nv_bfloat16* wq = g_Wb + rank * 25600;
#pragma unroll
        for (int u = 0; u < 13; u++) {
            int idx = tid + u * CNT;
            if (idx < 6400) {
                int ch = idx & 1;
                int r1 = idx >> 1;
                int n  = r1 % 160;
                int r2 = r1 / 160;
                int kc = r2 % 10;
                int pl = r2 / 10;
                const __nv_bfloat16* src = wq + pl * 102400 + kc * 2560 + n * 16 + ch * 8;
                uint32_t dst = wres + (uint32_t)(pl * WPL + kc * 5120 + n * 32
                                + ((ch ^ ((n >> 2) & 1)) << 4));
                cp16(dst, src);
            }
        }
        cpcommit();
    }
    for (int i = tid; i < 43008; i += CNT) hB[i] = __float2bfloat16(0.f);
#pragma unroll
    for (int j = 0; j < 5; j++) cst[j * CNT + tid] = 0.f;
    if (tid < TM) {
        int node = nodeBase + tid; if (node >= NN) node = NN - 1;
        srcS[tid] = esrc[node * DEG];
    }
    cpwait<0>();
    __syncthreads();
    cluster_sync();

    // per-lane B ldsm offsets (32B rows, XOR16 swizzle on (row>>2)&1)
    const int rowB4 = ng * 40 + ((lane >> 4) & 1) * 8 + (lane & 7);
    const uint32_t offB4 = (uint32_t)(rowB4 * 32 + ((((lane >> 3) & 1) ^ ((rowB4 >> 2) & 1)) << 4));
    const int rowB2 = ng * 40 + 32 + (lane & 7);
    const uint32_t offB2 = (uint32_t)(rowB2 * 32 + ((((lane >> 3) & 1) ^ ((rowB2 >> 2) & 1)) << 4));

    const int gb = rank * 160 + ng * 40 + q2 * 2;
    const int rw = mg * 16 + r8 + ((q2 & 1) ? 8 : 0);
    const int mBase = rank * 40 + ng * 10 + (q2 >> 1);

    float acc[5][4];

    for (int t = 0; t < DEG; t++) {
        // ---- acc init = gather P[src] (biases folded)
        {
            const int* sp = srcS + (t & 1) * 64;
            int rr = mg * 16 + r8;
            const float* p0 = g_P + (size_t)sp[rr] * 640 + gb;
            const float* p8 = g_P + (size_t)sp[rr + 8] * 640 + gb;
#pragma unroll
            for (int nt = 0; nt < 5; nt++) {
                float2 v0 = *(const float2*)(p0 + nt * 8);
                float2 v8 = *(const float2*)(p8 + nt * 8);
                acc[nt][0] = v0.x; acc[nt][1] = v0.y;
                acc[nt][2] = v8.x; acc[nt][3] = v8.y;
            }
        }
        if (t < DEG - 1 && tid < TM) {
            int node = nodeBase + tid; if (node >= NN) node = NN - 1;
            srcS[((t + 1) & 1) * 64 + tid] = esrc[node * DEG + t + 1];
        }

        // ---- 3-term MMA over full K=160, B resident
        const uint32_t aHiB = sbase + (uint32_t)((t & 1) * HBUF1)
                              + (uint32_t)((mg * 16 + lrow) * 336 + lkoff);
#pragma unroll
        for (int kc = 0; kc < 10; kc++) {
            uint32_t aH[4], aL[4];
            ldsm4(aH, aHiB + (uint32_t)(kc * 32));
            ldsm4(aL, aHiB + (uint32_t)(HPL + kc * 32));
            const uint32_t bkc = wres + (uint32_t)(kc * 5120);
            uint32_t bh01[4], bh23[4], bh4[2];
            ldsm4(bh01, bkc + offB4);
            ldsm4(bh23, bkc + offB4 + 512);
            ldsm2(bh4,  bkc + offB2);
            uint32_t bl01[4], bl23[4], bl4[2];
            ldsm4(bl01, bkc + WPL + offB4);
            ldsm4(bl23, bkc + WPL + offB4 + 512);
            ldsm2(bl4,  bkc + WPL + offB2);
            mma_bf16(acc[0], aH, bh01[0], bh01[1]);
            mma_bf16(acc[1], aH, bh01[2], bh01[3]);
            mma_bf16(acc[2], aH, bh23[0], bh23[1]);
            mma_bf16(acc[3], aH, bh23[2], bh23[3]);
            mma_bf16(acc[4], aH, bh4[0], bh4[1]);
            mma_bf16(acc[0], aL, bh01[0], bh01[1]);
            mma_bf16(acc[1], aL, bh01[2], bh01[3]);
            mma_bf16(acc[2], aL, bh23[0], bh23[1]);
            mma_bf16(acc[3], aL, bh23[2], bh23[3]);
            mma_bf16(acc[4], aL, bh4[0], bh4[1]);
            mma_bf16(acc[0], aH, bl01[0], bl01[1]);
            mma_bf16(acc[1], aH, bl01[2], bl01[3]);
            mma_bf16(acc[2], aH, bl23[0], bl23[1]);
            mma_bf16(acc[3], aH, bl23[2], bl23[3]);
            mma_bf16(acc[4], aH, bl4[0], bl4[1]);
        }

        // ---- pointwise (quarter = rank); gate exchange via shfl_xor(1)
        uint16_t hiA[5], loA[5];
#pragma unroll
        for (int nt = 0; nt < 5; nt++) {
            float ox = __shfl_xor_sync(0xffffffff, acc[nt][0], 1);
            float oy = __shfl_xor_sync(0xffffffff, acc[nt][1], 1);
            float oz = __shfl_xor_sync(0xffffffff, acc[nt][2], 1);
            float ow = __shfl_xor_sync(0xffffffff, acc[nt][3], 1);
            float gi, gf, gg, go;
            if (!(q2 & 1)) { gi = acc[nt][0]; gf = acc[nt][1]; gg = ox; go = oy; }
            else           { gi = oz; gf = ow; gg = acc[nt][2]; go = acc[nt][3]; }
            float cv = sigm(gf) * cst[nt * CNT + tid] + sigm(gi) * tanhfast(gg);
            cst[nt * CNT + tid] = cv;
            float hv = sigm(go) * tanhfast(cv);
            __nv_bfloat16 hh = __float2bfloat16(hv);
            __nv_bfloat16 hl = __float2bfloat16(hv - __bfloat162float(hh));
            hiA[nt] = reinterpret_cast<uint16_t&>(hh);
            loA[nt] = reinterpret_cast<uint16_t&>(hl);
        }
        // broadcast h quarter to all 4 CTAs (incl self) via DSMEM
        const uint32_t wb = (uint32_t)(((t + 1) & 1) * HBUF1 + rw * 336 + mBase * 2);
#pragma unroll
        for (uint32_t rk = 0; rk < 4; rk++) {
            uint32_t pb = mapa_rk(sbase, rk) + wb;
#pragma unroll
            for (int nt = 0; nt < 5; nt++) {
                stcl16(pb + (uint32_t)(nt * 4), hiA[nt]);
                stcl16(pb + (uint32_t)(HPL + nt * 4), loA[nt]);
            }
        }
        cluster_sync();
    }

    // ---- final layer: rank writes out cols [32*rank, 32*rank+32)
    const __nv_bfloat16* hf = hB;            // buf0 hi (t=16 even)
    const __nv_bfloat16* hl = hB + 10752;    // buf0 lo
    const int col = rank * 32 + lane;
#pragma unroll
    for (int rr = 0; rr < 4; rr++) {
        int row = warp * 4 + rr;
        int node = nodeBase + row;
        int nc = node < NN ? node : NN - 1;
        float qv = g_Q[(size_t)nc * OC + col];
        for (int k = 0; k < KHH; k++) {
            float a = __bfloat162float(hf[row * 168 + k]) +
                      __bfloat162float(hl[row * 168 + k]);
            qv = fmaf(a, g_WlP[k * OC + col], qv);
        }
        if (node < NN) out[(size_t)node * OC + col] = fmaxf(qv, 0.f);
    }
}

// ---------------- launch ----------------
extern "C" void kernel_launch(void* const* d_in, const int* in_sizes, int n_in,
                              void* d_out, int out_size) {
    const float* x    = (const float*)d_in[0];
    const int*   tids = (const int*)  d_in[1];
    const int*   eidx = (const int*)  d_in[2];
    const float* emb  = (const float*)d_in[3];
    const float* Wih  = (const float*)d_in[4];
    const float* Whh  = (const float*)d_in[5];
    const float* bih  = (const float*)d_in[6];
    const float* bhh  = (const float*)d_in[7];
    const float* Wl   = (const float*)d_in[8];
    const float* bl   = (const float*)d_in[9];
    const float* Wr   = (const float*)d_in[10];
    float* out = (float*)d_out;

    static bool attr_done = false;
    if (!attr_done) {
        cudaFuncSetAttribute(prep_PQ, cudaFuncAttributeMaxDynamicSharedMemorySize,
                             PTM * KHH * 4 + 2 * PCHB);
        cudaFuncSetAttribute(lstm_cluster, cudaFuncAttributeMaxDynamicSharedMemorySize,
                             SM_CL);
        attr_done = true;
    }

    prep_hin<<<(NN * FD + 255) / 256, 256>>>(x, tids, emb);
    prep_w<<<(2 * 4 * 10 * 160 * 16 + 255) / 256, 256>>>(Wih, Whh, bih, bhh, Wl, Wr);
    prep_PQ<<<(NN + PTM - 1) / PTM, PNT, PTM * KHH * 4 + 2 * PCHB>>>(bl);
    lstm_cluster<<<((NN + TM - 1) / TM) * 4, CNT, SM_CL>>>(eidx, out);
}

// round 16
// speedup vs baseline: 1.7072x; 1.7072x over previous
#include <cuda_runtime.h>
#include <cuda_bf16.h>
#include <cstdint>

#define NN   50000
#define DEG  16
#define FD   160
#define HD   160
#define GD   640
#define OC   128
#define KHH  160

// prep (fp32) config — proven machinery
#define PTM  64
#define PNT  512
#define PKC  16
#define PNCH (KHH/PKC)
#define PCHF (PKC*GD)
#define PCHB (PCHF*4)

// main MMA kernel config
#define TM   64
#define MNT  512                   // 16 warps = 4 M-groups x 4 N-groups
#define HPLANE 21504               // bytes per h plane (64*168*2)
#define HBUFB  43008               // bytes per h buffer (2 planes)
#define SM_B   86016               // B double buffer: 2 x 51200 (32B rows, XOR16)
#define BSTG   51200
#define SM_SRC 188416              // 2*64 ints
#define SM_MAIN 188928

typedef unsigned long long ull;

// ---------------- device scratch ----------------
__device__ float g_hin[NN * FD];
__device__ float g_WihP[KHH * HD * 4];   // [k][m][4]
__device__ float g_bias[GD];             // [m][4]
__device__ float g_WlP[KHH * OC];
__device__ float g_WrP[KHH * OC];
__device__ float g_P[NN * GD];           // [node][4m+g], biases folded
__device__ float g_Q[NN * OC];
// Whh bf16 split: [pl 2][q 4][kc 10][n 160][16]  (unpadded in gmem)
__device__ __align__(16) __nv_bfloat16 g_Wb[2 * 4 * 10 * 160 * 16];

// ---------------- helpers ----------------
__device__ __forceinline__ ull pack2(float lo, float hi) {
    ull v; asm("mov.b64 %0, {%1, %2};" : "=l"(v) : "f"(lo), "f"(hi)); return v;
}
__device__ __forceinline__ void unpack2(ull v, float& lo, float& hi) {
    asm("mov.b64 {%0, %1}, %2;" : "=f"(lo), "=f"(hi) : "l"(v));
}
__device__ __forceinline__ void fma2(ull& d, ull a, ull b) {
    asm("fma.rn.f32x2 %0, %1, %2, %0;" : "+l"(d) : "l"(a), "l"(b));
}
__device__ __forceinline__ void ldsv2(uint32_t a, ull& x, ull& y) {
    asm("ld.shared.v2.u64 {%0,%1}, [%2];" : "=l"(x), "=l"(y) : "r"(a));
}
__device__ __forceinline__ void ldsm4(uint32_t* r, uint32_t a) {
    asm volatile("ldmatrix.sync.aligned.m8n8.x4.shared.b16 {%0,%1,%2,%3}, [%4];"
                 : "=r"(r[0]), "=r"(r[1]), "=r"(r[2]), "=r"(r[3]) : "r"(a));
}
__device__ __forceinline__ void ldsm2(uint32_t* r, uint32_t a) {
    asm volatile("ldmatrix.sync.aligned.m8n8.x2.shared.b16 {%0,%1}, [%2];"
                 : "=r"(r[0]), "=r"(r[1]) : "r"(a));
}
__device__ __forceinline__ void cp16(uint32_t s, const void* g) {
    asm volatile("cp.async.ca.shared.global [%0], [%1], 16;" :: "r"(s), "l"(g));
}
__device__ __forceinline__ void cpcommit() { asm volatile("cp.async.commit_group;"); }
template<int N> __device__ __forceinline__ void cpwait() {
    asm volatile("cp.async.wait_group %0;" :: "n"(N));
}
__device__ __forceinline__ float sigm(float x) { return __fdividef(1.f, 1.f + __expf(-x)); }
__device__ __forceinline__ float tanhfast(float x) {
    return __fdividef(2.f, 1.f + __expf(-2.f * x)) - 1.f;
}
__device__ __forceinline__ void mma_bf16(float* d, const uint32_t* a, uint32_t b0, uint32_t b1) {
    asm volatile("mma.sync.aligned.m16n8k16.row.col.f32.bf16.bf16.f32 "
                 "{%0,%1,%2,%3}, {%4,%5,%6,%7}, {%8,%9}, {%0,%1,%2,%3};"
                 : "+f"(d[0]), "+f"(d[1]), "+f"(d[2]), "+f"(d[3])
                 : "r"(a[0]), "r"(a[1]), "r"(a[2]), "r"(a[3]), "r"(b0), "r"(b1));
}

// ---------------- prep kernels ----------------
__global__ void prep_hin(const float* __restrict__ x, const int* __restrict__ tids,
                         const float* __restrict__ emb) {
    int i = blockIdx.x * blockDim.x + threadIdx.x;
    if (i >= NN * FD) return;
    int n = i / FD, c = i % FD;
    g_hin[i] = (c < 128) ? x[n * 128 + c] : emb[tids[n] * 32 + (c - 128)];
}

// prep_w also builds the bf16 hi/lo split of Whh
__global__ void prep_w(const float* __restrict__ Wih, const float* __restrict__ Whh,
                       const float* __restrict__ bih, const float* __restrict__ bhh,
                       const float* __restrict__ Wl,  const float* __restrict__ Wr) {
    int i = blockIdx.x * blockDim.x + threadIdx.x;
    if (i < KHH * HD * 4) {
        int g = i & 3, m = (i >> 2) % HD, k = (i >> 2) / HD;
        g_WihP[i] = Wih[(g * HD + m) * FD + k];
    }
    if (i < GD) {
        int m = i >> 2, g = i & 3;
        g_bias[i] = bih[g * HD + m] + bhh[g * HD + m];
    }
    if (i < KHH * OC) {
        int k = i / OC, j = i % OC;
        g_WlP[i] = Wl[j * FD + k];
        g_WrP[i] = Wr[j * FD + k];
    }
    if (i < 2 * 4 * 10 * 160 * 16) {
        int kk = i & 15;
        int n  = (i >> 4) % 160;
        int kc = (i / 2560) % 10;
        int q  = (i / 25600) % 4;
        int pl = i / 102400;
        int k = kc * 16 + kk;
        int gcl = q * 160 + n;
        int m = gcl >> 2, g = gcl & 3;
        float w = Whh[(g * HD + m) * HD + k];
        __nv_bfloat16 hb = __float2bfloat16(w);
        g_Wb[i] = pl ? __float2bfloat16(w - __bfloat162float(hb)) : hb;
    }
}

// ---- prep_PQ: fp32 K=160 GEMM (proven) ----
__device__ __forceinline__ void pstage(const float* gsrc, uint32_t sdst, int tid) {
#pragma unroll
    for (int u = 0; u < 5; u++)
        cp16(sdst + (uint32_t)(tid * 16 + u * 8192), gsrc + tid * 4 + u * 2048);
    cpcommit();
}
__device__ __forceinline__ void pgemm(const float* __restrict__ gW, uint32_t wsbase,
                                      const float* __restrict__ hrow, int tid, int c,
                                      ull accIF[4][5], ull accGO[4][5]) {
    pstage(gW, wsbase, tid);
    pstage(gW + PCHF, wsbase + PCHB, tid);
    for (int ch = 0; ch < PNCH; ch++) {
        if (ch == PNCH - 1) cpwait<0>(); else cpwait<1>();
        __syncthreads();
        const uint32_t wb0 = wsbase + (uint32_t)(ch & 1) * PCHB;
#pragma unroll
        for (int kq = 0; kq < 4; kq++) {
            float4 a4[4];
#pragma unroll
            for (int i = 0; i < 4; i++)
                a4[i] = *(const float4*)&hrow[i * KHH + ch * PKC + kq * 4];
#pragma unroll
            for (int k2 = 0; k2 < 4; k2++) {
                ull a2[4];
#pragma unroll
                for (int i = 0; i < 4; i++) {
                    float a = (k2 == 0) ? a4[i].x : (k2 == 1) ? a4[i].y
                             : (k2 == 2) ? a4[i].z : a4[i].w;
                    a2[i] = pack2(a, a);
                }
                const uint32_t wb = wb0 + (uint32_t)((kq * 4 + k2) * 2560 + c * 16);
#pragma unroll
                for (int n = 0; n < 5; n++) {
                    ull wif, wgo;
                    ldsv2(wb + (uint32_t)(n * 512), wif, wgo);
#pragma unroll
                    for (int i = 0; i < 4; i++) {
                        fma2(accIF[i][n], a2[i], wif);
                        fma2(accGO[i][n], a2[i], wgo);
                    }
                }
            }
        }
        __syncthreads();
        if (ch < PNCH - 2) pstage(gW + (ch + 2) * PCHF, wsbase + (uint32_t)(ch & 1) * PCHB, tid);
    }
}

__global__ void __launch_bounds__(PNT, 1)
prep_PQ(const float* __restrict__ bl) {
    extern __shared__ float sm[];
    float* hs = sm;
    const uint32_t sbase = (uint32_t)__cvta_generic_to_shared(sm);
    const uint32_t wsbase = sbase + PTM * KHH * 4;
    const int tid = threadIdx.x, c = tid & 31, warp = tid >> 5;
    const int nodeBase = blockIdx.x * PTM;
    float* hrow = hs + warp * 4 * KHH;

#pragma unroll
    for (int u = 0; u < 5; u++) {
        int idx4 = tid + u * PNT;
        int r = idx4 / 40, col4 = idx4 % 40;
        int node = nodeBase + r; if (node >= NN) node = NN - 1;
        ((float4*)hs)[idx4] = ((const float4*)g_hin)[node * 40 + col4];
    }
    __syncthreads();

    ull accIF[4][5], accGO[4][5];
#pragma unroll
    for (int n = 0; n < 5; n++) {
        float4 b = ((const float4*)g_bias)[n * 32 + c];
#pragma unroll
        for (int i = 0; i < 4; i++) {
            accIF[i][n] = pack2(b.x, b.y);
            accGO[i][n] = pack2(b.z, b.w);
        }
    }
    pgemm(g_WihP, wsbase, hrow, tid, c, accIF, accGO);

#pragma unroll
    for (int i = 0; i < 4; i++) {
        int node = nodeBase + warp * 4 + i;
        if (node < NN) {
#pragma unroll
            for (int n = 0; n < 5; n++) {
                float4 o;
                unpack2(accIF[i][n], o.x, o.y);
                unpack2(accGO[i][n], o.z, o.w);
                ((float4*)g_P)[node * 160 + n * 32 + c] = o;
            }
        }
    }

    __syncthreads();
    float* Wfs = hs + PTM * KHH;
    for (int u = tid; u < KHH * OC / 4; u += PNT)
        ((float4*)Wfs)[u] = ((const float4*)g_WrP)[u];
    __syncthreads();

    float4 q[4];
    float4 blv = ((const float4*)bl)[c];
#pragma unroll
    for (int i = 0; i < 4; i++) q[i] = blv;
    for (int k = 0; k < KHH; k++) {
        float4 w = ((const float4*)Wfs)[k * 32 + c];
#pragma unroll
        for (int i = 0; i < 4; i++) {
            float a = hrow[i * KHH + k];
            q[i].x = fmaf(a, w.x, q[i].x);
            q[i].y = fmaf(a, w.y, q[i].y);
            q[i].z = fmaf(a, w.z, q[i].z);
            q[i].w = fmaf(a, w.w, q[i].w);
        }
    }
#pragma unroll
    for (int i = 0; i < 4; i++) {
        int node = nodeBase + warp * 4 + i;
        if (node < NN) ((float4*)g_Q)[node * 32 + c] = q[i];
    }
}

// ---------------- main MMA recurrence kernel ----------------
// stage = 51200B (one q, one plane: 10 kc x 160 n x 16 k), 32B rows XOR16-swizzled
// (layout + scatter + ldsm offsets validated in the round-15 resident-W kernel)
__device__ __forceinline__ void stageB51(uint32_t sdst, const __nv_bfloat16* g, int tid) {
#pragma unroll
    for (int u = 0; u < 7; u++) {
        int idx = tid + u * MNT;                 // 16B chunk id, 0..3199
        if (idx < 3200) {
            int ch = idx & 1;
            int r1 = idx >> 1;                   // 32B row id
            int n  = r1 % 160;
            int kc = r1 / 160;
            cp16(sdst + (uint32_t)(kc * 5120 + n * 32 + ((ch ^ ((n >> 2) & 1)) << 4)),
                 g + kc * 2560 + n * 16 + ch * 8);
        }
    }
    cpcommit();
}

__device__ __forceinline__ const __nv_bfloat16* bsrcM(int r) {
    // r in 0..7: q = r>>1, pl = r&1
    return g_Wb + (r & 1) * 102400 + (r >> 1) * 25600;
}

__global__ void __launch_bounds__(MNT)
lstm_main(const int* __restrict__ esrc, float* __restrict__ out) {
    extern __shared__ char smraw[];
    __nv_bfloat16* hB = (__nv_bfloat16*)smraw;       // [2buf][2pl][64][168]
    int*   srcS = (int*)(smraw + SM_SRC);            // [2][64]
    const uint32_t sbase = (uint32_t)__cvta_generic_to_shared(smraw);

    const int tid = threadIdx.x, lane = tid & 31, warp = tid >> 5;
    const int q2 = lane & 3, r8 = lane >> 2;
    const int mg = warp & 3, ng = warp >> 2;         // 4 M-groups x 4 N-groups
    const int lrow = lane & 15, lkoff = (lane >> 4) * 16;
    const int nodeBase = blockIdx.x * TM;

    for (int i = tid; i < 21504; i += MNT) hB[i] = __float2bfloat16(0.f);
    if (tid < TM) {
        int node = nodeBase + tid; if (node >= NN) node = NN - 1;
        srcS[tid] = esrc[node * DEG];
    }
    stageB51(sbase + SM_B, bsrcM(0), tid);
    stageB51(sbase + SM_B + BSTG, bsrcM(1), tid);

    // per-lane B ldsm offsets within a staged buffer (validated in round 15)
    const int rowB4 = ng * 40 + ((lane >> 4) & 1) * 8 + (lane & 7);
    const uint32_t offB4 = (uint32_t)(rowB4 * 32 + ((((lane >> 3) & 1) ^ ((rowB4 >> 2) & 1)) << 4));
    const int rowB2 = ng * 40 + 32 + (lane & 7);
    const uint32_t offB2 = (uint32_t)(rowB2 * 32 + ((((lane >> 3) & 1) ^ ((rowB2 >> 2) & 1)) << 4));

    float acc[5][4];
    uint32_t aC[10][4];
    float cst[4][5];
#pragma unroll
    for (int q = 0; q < 4; q++)
#pragma unroll
        for (int nt = 0; nt < 5; nt++) cst[q][nt] = 0.f;

    for (int t = 0; t < DEG; t++) {
        const uint32_t hRd = sbase + (uint32_t)(t & 1) * HBUFB;
        __nv_bfloat16* hWr = hB + ((t + 1) & 1) * 21504;
        const uint32_t aHiB = hRd + (uint32_t)((mg * 16 + lrow) * 336 + lkoff);

#pragma unroll
        for (int r = 0; r < 8; r++) {
            const int q = r >> 1;
            const int sIdx = t * 8 + r;
            if (t == DEG - 1 && r == 7) cpwait<0>(); else cpwait<1>();
            __syncthreads();
            const uint32_t bbuf = sbase + SM_B + (uint32_t)(sIdx & 1) * BSTG;

            if ((r & 1) == 0) {
                // ---- acc init from P (biases folded) for this q
                const int gb = q * 160 + ng * 40 + q2 * 2;
                const int* sp = srcS + (t & 1) * 64;
                int rr = mg * 16 + r8;
                const float* p0 = g_P + (size_t)sp[rr] * 640 + gb;
                const float* p8 = g_P + (size_t)sp[rr + 8] * 640 + gb;
#pragma unroll
                for (int nt = 0; nt < 5; nt++) {
                    float2 v0 = *(const float2*)(p0 + nt * 8);
                    float2 v8 = *(const float2*)(p8 + nt * 8);
                    acc[nt][0] = v0.x; acc[nt][1] = v0.y;
                    acc[nt][2] = v8.x; acc[nt][3] = v8.y;
                }
                if (q == 0 && t < DEG - 1 && tid < TM) {
                    int node = nodeBase + tid; if (node >= NN) node = NN - 1;
                    srcS[((t + 1) & 1) * 64 + tid] = esrc[node * DEG + t + 1];
                }
                // ---- hi plane: (A-hi + A-lo) x B-hi, cache A-hi for the lo stage
#pragma unroll
                for (int kc = 0; kc < 10; kc++) {
                    ldsm4(aC[kc], aHiB + (uint32_t)(kc * 32));
                    uint32_t aL[4];
                    ldsm4(aL, aHiB + (uint32_t)(HPLANE + kc * 32));
                    const uint32_t bkc = bbuf + (uint32_t)(kc * 5120);
                    uint32_t b01[4], b23[4], b4[2];
                    ldsm4(b01, bkc + offB4);
                    ldsm4(b23, bkc + offB4 + 512);
                    ldsm2(b4,  bkc + offB2);
                    mma_bf16(acc[0], aC[kc], b01[0], b01[1]);
                    mma_bf16(acc[1], aC[kc], b01[2], b01[3]);
                    mma_bf16(acc[2], aC[kc], b23[0], b23[1]);
                    mma_bf16(acc[3], aC[kc], b23[2], b23[3]);
                    mma_bf16(acc[4], aC[kc], b4[0], b4[1]);
                    mma_bf16(acc[0], aL, b01[0], b01[1]);
                    mma_bf16(acc[1], aL, b01[2], b01[3]);
                    mma_bf16(acc[2], aL, b23[0], b23[1]);
                    mma_bf16(acc[3], aL, b23[2], b23[3]);
                    mma_bf16(acc[4], aL, b4[0], b4[1]);
                }
            } else {
                // ---- lo plane: cached A-hi x B-lo (zero A loads)
#pragma unroll
                for (int kc = 0; kc < 10; kc++) {
                    const uint32_t bkc = bbuf + (uint32_t)(kc * 5120);
                    uint32_t b01[4], b23[4], b4[2];
                    ldsm4(b01, bkc + offB4);
                    ldsm4(b23, bkc + offB4 + 512);
                    ldsm2(b4,  bkc + offB2);
                    mma_bf16(acc[0], aC[kc], b01[0], b01[1]);
                    mma_bf16(acc[1], aC[kc], b01[2], b01[3]);
                    mma_bf16(acc[2], aC[kc], b23[0], b23[1]);
                    mma_bf16(acc[3], aC[kc], b23[2], b23[3]);
                    mma_bf16(acc[4], aC[kc], b4[0], b4[1]);
                }
                // ---- pointwise for quarter q; gate exchange via shfl_xor(1)
                int rw = mg * 16 + r8 + ((q2 & 1) ? 8 : 0);
#pragma unroll
                for (int nt = 0; nt < 5; nt++) {
                    float ox = __shfl_xor_sync(0xffffffff, acc[nt][0], 1);
                    float oy = __shfl_xor_sync(0xffffffff, acc[nt][1], 1);
                    float oz = __shfl_xor_sync(0xffffffff, acc[nt][2], 1);
                    float ow = __shfl_xor_sync(0xffffffff, acc[nt][3], 1);
                    float gi, gf, gg, go;
                    if (!(q2 & 1)) { gi = acc[nt][0]; gf = acc[nt][1]; gg = ox; go = oy; }
                    else           { gi = oz; gf = ow; gg = acc[nt][2]; go = acc[nt][3]; }
                    int m = q * 40 + ng * 10 + nt * 2 + (q2 >> 1);
                    float cv = sigm(gf) * cst[q][nt] + sigm(gi) * tanhfast(gg);
                    cst[q][nt] = cv;
                    float hv = sigm(go) * tanhfast(cv);
                    __nv_bfloat16 hh = __float2bfloat16(hv);
                    hWr[rw * 168 + m] = hh;
                    hWr[10752 + rw * 168 + m] = __float2bfloat16(hv - __bfloat162float(hh));
                }
            }
            __syncthreads();
            if (sIdx + 2 < DEG * 8) {
                stageB51(sbase + SM_B + (uint32_t)(sIdx & 1) * BSTG, bsrcM((r + 2) & 7), tid);
            }
        }
    }

    // ---- final layer: out = relu(Q[node] + h @ Wl^T); h last in buf0
    __syncthreads();
    const __nv_bfloat16* hf = hB;
    const __nv_bfloat16* hl = hB + 10752;
#pragma unroll
    for (int rr = 0; rr < 4; rr++) {
        int row = warp * 4 + rr;
        int node = nodeBase + row;
        int nc = node < NN ? node : NN - 1;
        float4 qv = ((const float4*)g_Q)[nc * 32 + lane];
        for (int k = 0; k < KHH; k++) {
            float a = __bfloat162float(hf[row * 168 + k]) +
                      __bfloat162float(hl[row * 168 + k]);
            float4 w = *(const float4*)&g_WlP[k * OC + lane * 4];
            qv.x = fmaf(a, w.x, qv.x);
            qv.y = fmaf(a, w.y, qv.y);
            qv.z = fmaf(a, w.z, qv.z);
            qv.w = fmaf(a, w.w, qv.w);
        }
        if (node < NN) {
            float4 o;
            o.x = fmaxf(qv.x, 0.f); o.y = fmaxf(qv.y, 0.f);
            o.z = fmaxf(qv.z, 0.f); o.w = fmaxf(qv.w, 0.f);
            ((float4*)out)[node * 32 + lane] = o;
        }
    }
}

// ---------------- launch ----------------
extern "C" void kernel_launch(void* const* d_in, const int* in_sizes, int n_in,
                              void* d_out, int out_size) {
    const float* x    = (const float*)d_in[0];
    const int*   tids = (const int*)  d_in[1];
    const int*   eidx = (const int*)  d_in[2];
    const float* emb  = (const float*)d_in[3];
    const float* Wih  = (const float*)d_in[4];
    const float* Whh  = (const float*)d_in[5];
    const float* bih  = (const float*)d_in[6];
    const float* bhh  = (const float*)d_in[7];
    const float* Wl   = (const float*)d_in[8];
    const float* bl   = (const float*)d_in[9];
    const float* Wr   = (const float*)d_in[10];
    float* out = (float*)d_out;

    static bool attr_done = false;
    if (!attr_done) {
        cudaFuncSetAttribute(prep_PQ, cudaFuncAttributeMaxDynamicSharedMemorySize,
                             PTM * KHH * 4 + 2 * PCHB);
        cudaFuncSetAttribute(lstm_main, cudaFuncAttributeMaxDynamicSharedMemorySize,
                             SM_MAIN);
        attr_done = true;
    }

    prep_hin<<<(NN * FD + 255) / 256, 256>>>(x, tids, emb);
    prep_w<<<(2 * 4 * 10 * 160 * 16 + 255) / 256, 256>>>(Wih, Whh, bih, bhh, Wl, Wr);
    prep_PQ<<<(NN + PTM - 1) / PTM, PNT, PTM * KHH * 4 + 2 * PCHB>>>(bl);
    lstm_main<<<(NN + TM - 1) / TM, MNT, SM_MAIN>>>(eidx, out);
}